// round 1
// baseline (speedup 1.0000x reference)
#include <cuda_runtime.h>
#include <cuda_bf16.h>
#include <cstdint>

// Problem constants
#define BB 2
#define SS 2048
#define DD 1024
#define HH 16
#define HD 64
#define BH (BB*HH)          // 32
#define MROWS (BB*SS)       // 4096
#define E3D (3*DD)          // 3072

// Scratch (device globals; allocation-free kernel_launch)
__device__ float g_Q[(size_t)BH * SS * HD];        // 16 MB
__device__ float g_K[(size_t)BH * SS * HD];        // 16 MB
__device__ float g_V[(size_t)BH * SS * HD];        // 16 MB
__device__ float g_L[(size_t)BH * SS * SS];        // 512 MB
__device__ float4 g_stats[(size_t)BH * SS];        // {m, cut, invZ2, u}
__device__ float g_vals[(size_t)MROWS * DD];       // 16 MB

// ---------------------------------------------------------------------------
// Kernel 1: QKV projection. C[m,e] = sum_k X[m,k]*W[e,k] + b[e], scattered
// into Q/K/V with [B,H,S,HD] layout. 128x128x8 tile, 256 threads, 8x8/thread.
// ---------------------------------------------------------------------------
__global__ __launch_bounds__(256) void qkv_gemm_kernel(
    const float* __restrict__ X, const float* __restrict__ W,
    const float* __restrict__ bias)
{
    __shared__ float As[8][128];
    __shared__ float Bs[8][128];
    const int K = DD;
    const int m0 = blockIdx.x * 128;
    const int e0 = blockIdx.y * 128;
    const int tid = threadIdx.x;
    const int loadRow = tid >> 1;
    const int loadK = (tid & 1) * 4;
    const int ty = tid >> 4, tx = tid & 15;

    float acc[8][8];
    #pragma unroll
    for (int i = 0; i < 8; i++)
        #pragma unroll
        for (int j = 0; j < 8; j++) acc[i][j] = 0.f;

    for (int k0 = 0; k0 < K; k0 += 8) {
        float4 a = *(const float4*)(X + (size_t)(m0 + loadRow) * K + k0 + loadK);
        float4 b = *(const float4*)(W + (size_t)(e0 + loadRow) * K + k0 + loadK);
        __syncthreads();
        As[loadK+0][loadRow] = a.x; As[loadK+1][loadRow] = a.y;
        As[loadK+2][loadRow] = a.z; As[loadK+3][loadRow] = a.w;
        Bs[loadK+0][loadRow] = b.x; Bs[loadK+1][loadRow] = b.y;
        Bs[loadK+2][loadRow] = b.z; Bs[loadK+3][loadRow] = b.w;
        __syncthreads();
        #pragma unroll
        for (int kk = 0; kk < 8; ++kk) {
            float a8[8], b8[8];
            #pragma unroll
            for (int i = 0; i < 8; i += 4) {
                *(float4*)(a8 + i) = *(const float4*)(&As[kk][ty * 8 + i]);
                *(float4*)(b8 + i) = *(const float4*)(&Bs[kk][tx * 8 + i]);
            }
            #pragma unroll
            for (int i = 0; i < 8; ++i)
                #pragma unroll
                for (int j = 0; j < 8; ++j)
                    acc[i][j] = fmaf(a8[i], b8[j], acc[i][j]);
        }
    }

    #pragma unroll
    for (int i = 0; i < 8; ++i) {
        const int m = m0 + ty * 8 + i;
        const int b = m >> 11;          // /S
        const int s = m & (SS - 1);
        #pragma unroll
        for (int j = 0; j < 8; ++j) {
            const int e = e0 + tx * 8 + j;
            const float v = acc[i][j] + bias[e];
            const int h = e / (3 * HD);
            const int c = e % (3 * HD);
            const size_t idx = ((((size_t)b * HH + h) * SS + s) * HD) + (c & (HD - 1));
            if (c < HD)            g_Q[idx] = v;
            else if (c < 2 * HD)   g_K[idx] = v;
            else                   g_V[idx] = v;
        }
    }
}

// ---------------------------------------------------------------------------
// Kernel 2: logits L[bh,q,k] = scale * dot(Q[bh,q,:], K[bh,k,:]).
// Same 128x128 tile shape, K=64.
// ---------------------------------------------------------------------------
__global__ __launch_bounds__(256) void logits_kernel()
{
    __shared__ float As[8][128];
    __shared__ float Bs[8][128];
    const int bh = blockIdx.z;
    const float* Qb = g_Q + (size_t)bh * SS * HD;
    const float* Kb = g_K + (size_t)bh * SS * HD;
    const int m0 = blockIdx.x * 128;
    const int n0 = blockIdx.y * 128;
    const int tid = threadIdx.x;
    const int loadRow = tid >> 1;
    const int loadK = (tid & 1) * 4;
    const int ty = tid >> 4, tx = tid & 15;
    const float scale = 0.125f;   // 1/sqrt(64)

    float acc[8][8];
    #pragma unroll
    for (int i = 0; i < 8; i++)
        #pragma unroll
        for (int j = 0; j < 8; j++) acc[i][j] = 0.f;

    for (int k0 = 0; k0 < HD; k0 += 8) {
        float4 a = *(const float4*)(Qb + (size_t)(m0 + loadRow) * HD + k0 + loadK);
        float4 b = *(const float4*)(Kb + (size_t)(n0 + loadRow) * HD + k0 + loadK);
        __syncthreads();
        As[loadK+0][loadRow] = a.x; As[loadK+1][loadRow] = a.y;
        As[loadK+2][loadRow] = a.z; As[loadK+3][loadRow] = a.w;
        Bs[loadK+0][loadRow] = b.x; Bs[loadK+1][loadRow] = b.y;
        Bs[loadK+2][loadRow] = b.z; Bs[loadK+3][loadRow] = b.w;
        __syncthreads();
        #pragma unroll
        for (int kk = 0; kk < 8; ++kk) {
            float a8[8], b8[8];
            #pragma unroll
            for (int i = 0; i < 8; i += 4) {
                *(float4*)(a8 + i) = *(const float4*)(&As[kk][ty * 8 + i]);
                *(float4*)(b8 + i) = *(const float4*)(&Bs[kk][tx * 8 + i]);
            }
            #pragma unroll
            for (int i = 0; i < 8; ++i)
                #pragma unroll
                for (int j = 0; j < 8; ++j)
                    acc[i][j] = fmaf(a8[i], b8[j], acc[i][j]);
        }
    }

    float* Lb = g_L + (size_t)bh * SS * SS;
    #pragma unroll
    for (int i = 0; i < 8; ++i) {
        const int q = m0 + ty * 8 + i;
        float4 v0, v1;
        v0.x = acc[i][0]*scale; v0.y = acc[i][1]*scale;
        v0.z = acc[i][2]*scale; v0.w = acc[i][3]*scale;
        v1.x = acc[i][4]*scale; v1.y = acc[i][5]*scale;
        v1.z = acc[i][6]*scale; v1.w = acc[i][7]*scale;
        float* p = Lb + (size_t)q * SS + n0 + tx * 8;
        *(float4*)p = v0;
        *(float4*)(p + 4) = v1;
    }
}

// ---------------------------------------------------------------------------
// Kernel 3: per-row softmax stats. One block per (bh, q) row; row cached in
// SMEM. Produces {m, cut, invZ2, u}:
//   normal row : cut = m + log(thr*Z1), invZ2 = 1/sum_{l>cut} exp(l-m), u = 0
//   all masked : cut = +inf, u = 1/S (second softmax degenerates to uniform)
// ---------------------------------------------------------------------------
__device__ __forceinline__ float block_reduce_max(float v, float* sred) {
    #pragma unroll
    for (int o = 16; o > 0; o >>= 1) v = fmaxf(v, __shfl_xor_sync(0xffffffffu, v, o));
    const int w = threadIdx.x >> 5;
    if ((threadIdx.x & 31) == 0) sred[w] = v;
    __syncthreads();
    if (threadIdx.x < 32) {
        float x = (threadIdx.x < 8) ? sred[threadIdx.x] : -3.4e38f;
        #pragma unroll
        for (int o = 4; o > 0; o >>= 1) x = fmaxf(x, __shfl_xor_sync(0xffffffffu, x, o));
        if (threadIdx.x == 0) sred[0] = x;
    }
    __syncthreads();
    v = sred[0];
    __syncthreads();
    return v;
}

__device__ __forceinline__ float block_reduce_sum(float v, float* sred) {
    #pragma unroll
    for (int o = 16; o > 0; o >>= 1) v += __shfl_xor_sync(0xffffffffu, v, o);
    const int w = threadIdx.x >> 5;
    if ((threadIdx.x & 31) == 0) sred[w] = v;
    __syncthreads();
    if (threadIdx.x < 32) {
        float x = (threadIdx.x < 8) ? sred[threadIdx.x] : 0.f;
        #pragma unroll
        for (int o = 4; o > 0; o >>= 1) x += __shfl_xor_sync(0xffffffffu, x, o);
        if (threadIdx.x == 0) sred[0] = x;
    }
    __syncthreads();
    v = sred[0];
    __syncthreads();
    return v;
}

__global__ __launch_bounds__(256) void rowstats_kernel(const float* __restrict__ thrs)
{
    __shared__ float buf[SS];
    __shared__ float sred[8];
    const int row = blockIdx.x;              // bh*S + q
    const int h = (row >> 11) & (HH - 1);
    const float thr = thrs[h];
    const float* Lrow = g_L + (size_t)row * SS;
    const int tid = threadIdx.x;

    float4* b4 = (float4*)buf;
    const float4* l4 = (const float4*)Lrow;
    #pragma unroll
    for (int i = tid; i < SS / 4; i += 256) b4[i] = l4[i];
    __syncthreads();

    float mx = -3.4e38f;
    #pragma unroll
    for (int i = tid; i < SS; i += 256) mx = fmaxf(mx, buf[i]);
    const float m = block_reduce_max(mx, sred);

    float z = 0.f;
    #pragma unroll
    for (int i = tid; i < SS; i += 256) z += __expf(buf[i] - m);
    const float Z1 = block_reduce_sum(z, sred);

    const float tz = thr * Z1;
    if (tz >= 1.0f) {
        if (tid == 0) {
            float4 st; st.x = 0.f; st.y = __int_as_float(0x7f800000); // +inf
            st.z = 0.f; st.w = 1.0f / (float)SS;
            g_stats[row] = st;
        }
        return;
    }
    const float cut = m + logf(tz);
    float z2 = 0.f;
    #pragma unroll
    for (int i = tid; i < SS; i += 256) {
        const float l = buf[i];
        if (l > cut) z2 += __expf(l - m);
    }
    const float Z2 = block_reduce_sum(z2, sred);
    if (tid == 0) {
        float4 st; st.x = m; st.y = cut; st.z = 1.0f / Z2; st.w = 0.f;
        g_stats[row] = st;
    }
}

// ---------------------------------------------------------------------------
// Kernel 4: PV GEMM with inline weight transform.
// out[bh,q,hd] = sum_k w(q,k) * V[bh,k,hd],  w = (l>cut)?exp(l-m)*invZ2 : u
// Tile 128(q) x 64(hd) x 16(k), 256 threads, 8x4/thread.
// Writes to g_vals in [B,S,H,HD] layout for the O projection.
// ---------------------------------------------------------------------------
__global__ __launch_bounds__(256) void pv_kernel()
{
    __shared__ float As[16][128];
    __shared__ float Bs[16][64];
    __shared__ float4 st_s[128];
    const int bh = blockIdx.y;
    const int q0 = blockIdx.x * 128;
    const float* Lb = g_L + (size_t)bh * SS * SS;
    const float* Vb = g_V + (size_t)bh * SS * HD;
    const int tid = threadIdx.x;

    if (tid < 128) st_s[tid] = g_stats[(size_t)bh * SS + q0 + tid];
    __syncthreads();

    const int aRow = tid >> 1;            // 0..127 (q within tile)
    const int aK = (tid & 1) * 8;         // 0 or 8
    const float4 myst = st_s[aRow];       // {m, cut, invZ2, u}
    const int bRow = tid >> 4;            // 0..15 (k within tile)
    const int bCol = (tid & 15) * 4;      // 0..60
    const int ty = tid >> 4, tx = tid & 15;

    float acc[8][4];
    #pragma unroll
    for (int i = 0; i < 8; i++)
        #pragma unroll
        for (int j = 0; j < 4; j++) acc[i][j] = 0.f;

    for (int kt = 0; kt < SS; kt += 16) {
        float4 a0 = *(const float4*)(Lb + (size_t)(q0 + aRow) * SS + kt + aK);
        float4 a1 = *(const float4*)(Lb + (size_t)(q0 + aRow) * SS + kt + aK + 4);
        float4 bv = *(const float4*)(Vb + (size_t)(kt + bRow) * HD + bCol);
        __syncthreads();
        float av[8] = {a0.x, a0.y, a0.z, a0.w, a1.x, a1.y, a1.z, a1.w};
        #pragma unroll
        for (int i = 0; i < 8; ++i) {
            const float l = av[i];
            const float w = (l > myst.y) ? __expf(l - myst.x) * myst.z : myst.w;
            As[aK + i][aRow] = w;
        }
        *(float4*)(&Bs[bRow][bCol]) = bv;
        __syncthreads();
        #pragma unroll
        for (int kk = 0; kk < 16; ++kk) {
            float a8[8], b4[4];
            #pragma unroll
            for (int i = 0; i < 8; i += 4)
                *(float4*)(a8 + i) = *(const float4*)(&As[kk][ty * 8 + i]);
            *(float4*)b4 = *(const float4*)(&Bs[kk][tx * 4]);
            #pragma unroll
            for (int i = 0; i < 8; ++i)
                #pragma unroll
                for (int j = 0; j < 4; ++j)
                    acc[i][j] = fmaf(a8[i], b4[j], acc[i][j]);
        }
    }

    const int b = bh >> 4;           // / H
    const int h = bh & (HH - 1);
    #pragma unroll
    for (int i = 0; i < 8; ++i) {
        const int s = q0 + ty * 8 + i;
        float* p = g_vals + (((size_t)(b * SS + s) * HH + h) * HD) + tx * 4;
        float4 v; v.x = acc[i][0]; v.y = acc[i][1]; v.z = acc[i][2]; v.w = acc[i][3];
        *(float4*)p = v;
    }
}

// ---------------------------------------------------------------------------
// Kernel 5: output projection. out[m,n] = sum_k vals[m,k]*OW[n,k] + ob[n]
// ---------------------------------------------------------------------------
__global__ __launch_bounds__(256) void oproj_kernel(
    const float* __restrict__ OW, const float* __restrict__ ob,
    float* __restrict__ out)
{
    __shared__ float As[8][128];
    __shared__ float Bs[8][128];
    const int K = DD, N = DD;
    const int m0 = blockIdx.x * 128;
    const int n0 = blockIdx.y * 128;
    const int tid = threadIdx.x;
    const int loadRow = tid >> 1;
    const int loadK = (tid & 1) * 4;
    const int ty = tid >> 4, tx = tid & 15;

    float acc[8][8];
    #pragma unroll
    for (int i = 0; i < 8; i++)
        #pragma unroll
        for (int j = 0; j < 8; j++) acc[i][j] = 0.f;

    for (int k0 = 0; k0 < K; k0 += 8) {
        float4 a = *(const float4*)(g_vals + (size_t)(m0 + loadRow) * K + k0 + loadK);
        float4 b = *(const float4*)(OW + (size_t)(n0 + loadRow) * K + k0 + loadK);
        __syncthreads();
        As[loadK+0][loadRow] = a.x; As[loadK+1][loadRow] = a.y;
        As[loadK+2][loadRow] = a.z; As[loadK+3][loadRow] = a.w;
        Bs[loadK+0][loadRow] = b.x; Bs[loadK+1][loadRow] = b.y;
        Bs[loadK+2][loadRow] = b.z; Bs[loadK+3][loadRow] = b.w;
        __syncthreads();
        #pragma unroll
        for (int kk = 0; kk < 8; ++kk) {
            float a8[8], b8[8];
            #pragma unroll
            for (int i = 0; i < 8; i += 4) {
                *(float4*)(a8 + i) = *(const float4*)(&As[kk][ty * 8 + i]);
                *(float4*)(b8 + i) = *(const float4*)(&Bs[kk][tx * 8 + i]);
            }
            #pragma unroll
            for (int i = 0; i < 8; ++i)
                #pragma unroll
                for (int j = 0; j < 8; ++j)
                    acc[i][j] = fmaf(a8[i], b8[j], acc[i][j]);
        }
    }

    #pragma unroll
    for (int i = 0; i < 8; ++i) {
        const int m = m0 + ty * 8 + i;
        #pragma unroll
        for (int j = 0; j < 8; j += 4) {
            const int n = n0 + tx * 8 + j;
            float4 v;
            v.x = acc[i][j+0] + ob[n+0];
            v.y = acc[i][j+1] + ob[n+1];
            v.z = acc[i][j+2] + ob[n+2];
            v.w = acc[i][j+3] + ob[n+3];
            *(float4*)(out + (size_t)m * N + n) = v;
        }
    }
}

// ---------------------------------------------------------------------------
extern "C" void kernel_launch(void* const* d_in, const int* in_sizes, int n_in,
                              void* d_out, int out_size)
{
    const float *x = nullptr, *thr = nullptr, *qkvw = nullptr,
                *qkvb = nullptr, *ow = nullptr, *ob = nullptr;
    for (int i = 0; i < n_in; ++i) {
        const float* p = (const float*)d_in[i];
        switch (in_sizes[i]) {
            case MROWS * DD:   x = p;    break;   // 4,194,304
            case HH:           thr = p;  break;   // 16
            case E3D * DD:     qkvw = p; break;   // 3,145,728
            case E3D:          qkvb = p; break;   // 3,072
            case DD * DD:      ow = p;   break;   // 1,048,576
            case DD:           ob = p;   break;   // 1,024
        }
    }
    float* out = (float*)d_out;

    qkv_gemm_kernel<<<dim3(MROWS / 128, E3D / 128), 256>>>(x, qkvw, qkvb);
    logits_kernel<<<dim3(SS / 128, SS / 128, BH), 256>>>();
    rowstats_kernel<<<BH * SS, 256>>>(thr);
    pv_kernel<<<dim3(SS / 128, BH), 256>>>();
    oproj_kernel<<<dim3(MROWS / 128, DD / 128), 256>>>(ow, ob, out);
}

// round 3
// speedup vs baseline: 1.2099x; 1.2099x over previous
#include <cuda_runtime.h>
#include <cuda_bf16.h>
#include <cstdint>

// Problem constants
#define BB 2
#define SS 2048
#define DD 1024
#define HH 16
#define HD 64
#define BH (BB*HH)          // 32
#define MROWS (BB*SS)       // 4096
#define E3D (3*DD)          // 3072

// Scratch (device globals; allocation-free kernel_launch)
__device__ float g_Q[(size_t)BH * SS * HD];            // 16 MB
__device__ float g_K[(size_t)BH * SS * HD];            // 16 MB
__device__ float g_V[(size_t)BH * SS * HD];            // 16 MB
__device__ float g_L[(size_t)BH * SS * SS];            // 512 MB
__device__ float4 g_stats[(size_t)BH * SS];            // {m, cut, invZ2, u}
__device__ __nv_bfloat16 g_Vhi[(size_t)BH * HD * SS];  // V^T hi [bh][hd][s]
__device__ __nv_bfloat16 g_Vlo[(size_t)BH * HD * SS];  // V^T lo
__device__ __nv_bfloat16 g_valsS[(size_t)MROWS * E3D]; // vals split [hi|hi|lo], 24MB
__device__ __nv_bfloat16 g_OWs[(size_t)DD * E3D];      // o_w split  [hi|lo|hi], 6MB

// ===========================================================================
// Helpers
// ===========================================================================
__device__ __forceinline__ uint32_t smem_u32(const void* p) {
    uint32_t a;
    asm("{ .reg .u64 t; cvta.to.shared.u64 t, %1; cvt.u32.u64 %0, t; }" : "=r"(a) : "l"(p));
    return a;
}
__device__ __forceinline__ uint32_t pack16(uint16_t a, uint16_t b) {
    return (uint32_t)a | ((uint32_t)b << 16);
}
__device__ __forceinline__ void split_bf(float x, uint16_t& h, uint16_t& l) {
    __nv_bfloat16 hb = __float2bfloat16(x);
    float r = x - __bfloat162float(hb);
    __nv_bfloat16 lb = __float2bfloat16(r);
    h = *reinterpret_cast<uint16_t*>(&hb);
    l = *reinterpret_cast<uint16_t*>(&lb);
}
__device__ __forceinline__ uint32_t pk2(float a, float b) {
    __nv_bfloat162 h = __floats2bfloat162_rn(a, b);
    return *reinterpret_cast<uint32_t*>(&h);
}

__device__ __forceinline__ void ldsm4(uint32_t* r, uint32_t addr) {
    asm volatile("ldmatrix.sync.aligned.m8n8.x4.shared.b16 {%0,%1,%2,%3}, [%4];"
                 : "=r"(r[0]), "=r"(r[1]), "=r"(r[2]), "=r"(r[3]) : "r"(addr));
}
__device__ __forceinline__ void mma16816(float* c, const uint32_t* a,
                                         uint32_t b0, uint32_t b1) {
    asm volatile(
        "mma.sync.aligned.m16n8k16.row.col.f32.bf16.bf16.f32 "
        "{%0,%1,%2,%3}, {%4,%5,%6,%7}, {%8,%9}, {%0,%1,%2,%3};"
        : "+f"(c[0]), "+f"(c[1]), "+f"(c[2]), "+f"(c[3])
        : "r"(a[0]), "r"(a[1]), "r"(a[2]), "r"(a[3]), "r"(b0), "r"(b1));
}

#define TSTRIDE 40   // bf16 elements per smem tile row (80B, conflict-free ldmatrix)

// ===========================================================================
// Kernel 1: QKV projection (fp32 SIMT — precision-critical)
// ===========================================================================
__global__ __launch_bounds__(256) void qkv_gemm_kernel(
    const float* __restrict__ X, const float* __restrict__ W,
    const float* __restrict__ bias)
{
    __shared__ float As[8][128];
    __shared__ float Bs[8][128];
    const int K = DD;
    const int m0 = blockIdx.x * 128;
    const int e0 = blockIdx.y * 128;
    const int tid = threadIdx.x;
    const int loadRow = tid >> 1;
    const int loadK = (tid & 1) * 4;
    const int ty = tid >> 4, tx = tid & 15;

    float acc[8][8];
    #pragma unroll
    for (int i = 0; i < 8; i++)
        #pragma unroll
        for (int j = 0; j < 8; j++) acc[i][j] = 0.f;

    for (int k0 = 0; k0 < K; k0 += 8) {
        float4 a = *(const float4*)(X + (size_t)(m0 + loadRow) * K + k0 + loadK);
        float4 b = *(const float4*)(W + (size_t)(e0 + loadRow) * K + k0 + loadK);
        __syncthreads();
        As[loadK+0][loadRow] = a.x; As[loadK+1][loadRow] = a.y;
        As[loadK+2][loadRow] = a.z; As[loadK+3][loadRow] = a.w;
        Bs[loadK+0][loadRow] = b.x; Bs[loadK+1][loadRow] = b.y;
        Bs[loadK+2][loadRow] = b.z; Bs[loadK+3][loadRow] = b.w;
        __syncthreads();
        #pragma unroll
        for (int kk = 0; kk < 8; ++kk) {
            float a8[8], b8[8];
            #pragma unroll
            for (int i = 0; i < 8; i += 4) {
                *(float4*)(a8 + i) = *(const float4*)(&As[kk][ty * 8 + i]);
                *(float4*)(b8 + i) = *(const float4*)(&Bs[kk][tx * 8 + i]);
            }
            #pragma unroll
            for (int i = 0; i < 8; ++i)
                #pragma unroll
                for (int j = 0; j < 8; ++j)
                    acc[i][j] = fmaf(a8[i], b8[j], acc[i][j]);
        }
    }

    #pragma unroll
    for (int i = 0; i < 8; ++i) {
        const int m = m0 + ty * 8 + i;
        const int b = m >> 11;
        const int s = m & (SS - 1);
        #pragma unroll
        for (int j = 0; j < 8; ++j) {
            const int e = e0 + tx * 8 + j;
            const float v = acc[i][j] + bias[e];
            const int h = e / (3 * HD);
            const int c = e % (3 * HD);
            const size_t idx = ((((size_t)b * HH + h) * SS + s) * HD) + (c & (HD - 1));
            if (c < HD)            g_Q[idx] = v;
            else if (c < 2 * HD)   g_K[idx] = v;
            else                   g_V[idx] = v;
        }
    }
}

// ===========================================================================
// Kernel 2: logits (fp32 SIMT — precision-critical)
// ===========================================================================
__global__ __launch_bounds__(256) void logits_kernel()
{
    __shared__ float As[8][128];
    __shared__ float Bs[8][128];
    const int bh = blockIdx.z;
    const float* Qb = g_Q + (size_t)bh * SS * HD;
    const float* Kb = g_K + (size_t)bh * SS * HD;
    const int m0 = blockIdx.x * 128;
    const int n0 = blockIdx.y * 128;
    const int tid = threadIdx.x;
    const int loadRow = tid >> 1;
    const int loadK = (tid & 1) * 4;
    const int ty = tid >> 4, tx = tid & 15;
    const float scale = 0.125f;

    float acc[8][8];
    #pragma unroll
    for (int i = 0; i < 8; i++)
        #pragma unroll
        for (int j = 0; j < 8; j++) acc[i][j] = 0.f;

    for (int k0 = 0; k0 < HD; k0 += 8) {
        float4 a = *(const float4*)(Qb + (size_t)(m0 + loadRow) * HD + k0 + loadK);
        float4 b = *(const float4*)(Kb + (size_t)(n0 + loadRow) * HD + k0 + loadK);
        __syncthreads();
        As[loadK+0][loadRow] = a.x; As[loadK+1][loadRow] = a.y;
        As[loadK+2][loadRow] = a.z; As[loadK+3][loadRow] = a.w;
        Bs[loadK+0][loadRow] = b.x; Bs[loadK+1][loadRow] = b.y;
        Bs[loadK+2][loadRow] = b.z; Bs[loadK+3][loadRow] = b.w;
        __syncthreads();
        #pragma unroll
        for (int kk = 0; kk < 8; ++kk) {
            float a8[8], b8[8];
            #pragma unroll
            for (int i = 0; i < 8; i += 4) {
                *(float4*)(a8 + i) = *(const float4*)(&As[kk][ty * 8 + i]);
                *(float4*)(b8 + i) = *(const float4*)(&Bs[kk][tx * 8 + i]);
            }
            #pragma unroll
            for (int i = 0; i < 8; ++i)
                #pragma unroll
                for (int j = 0; j < 8; ++j)
                    acc[i][j] = fmaf(a8[i], b8[j], acc[i][j]);
        }
    }

    float* Lb = g_L + (size_t)bh * SS * SS;
    #pragma unroll
    for (int i = 0; i < 8; ++i) {
        const int q = m0 + ty * 8 + i;
        float4 v0, v1;
        v0.x = acc[i][0]*scale; v0.y = acc[i][1]*scale;
        v0.z = acc[i][2]*scale; v0.w = acc[i][3]*scale;
        v1.x = acc[i][4]*scale; v1.y = acc[i][5]*scale;
        v1.z = acc[i][6]*scale; v1.w = acc[i][7]*scale;
        float* p = Lb + (size_t)q * SS + n0 + tx * 8;
        *(float4*)p = v0;
        *(float4*)(p + 4) = v1;
    }
}

// ===========================================================================
// Kernel 3: per-row softmax stats -> {m, cut, invZ2, u}
// ===========================================================================
__device__ __forceinline__ float block_reduce_max(float v, float* sred) {
    #pragma unroll
    for (int o = 16; o > 0; o >>= 1) v = fmaxf(v, __shfl_xor_sync(0xffffffffu, v, o));
    const int w = threadIdx.x >> 5;
    if ((threadIdx.x & 31) == 0) sred[w] = v;
    __syncthreads();
    if (threadIdx.x < 32) {
        float x = (threadIdx.x < 8) ? sred[threadIdx.x] : -3.4e38f;
        #pragma unroll
        for (int o = 4; o > 0; o >>= 1) x = fmaxf(x, __shfl_xor_sync(0xffffffffu, x, o));
        if (threadIdx.x == 0) sred[0] = x;
    }
    __syncthreads();
    v = sred[0];
    __syncthreads();
    return v;
}
__device__ __forceinline__ float block_reduce_sum(float v, float* sred) {
    #pragma unroll
    for (int o = 16; o > 0; o >>= 1) v += __shfl_xor_sync(0xffffffffu, v, o);
    const int w = threadIdx.x >> 5;
    if ((threadIdx.x & 31) == 0) sred[w] = v;
    __syncthreads();
    if (threadIdx.x < 32) {
        float x = (threadIdx.x < 8) ? sred[threadIdx.x] : 0.f;
        #pragma unroll
        for (int o = 4; o > 0; o >>= 1) x += __shfl_xor_sync(0xffffffffu, x, o);
        if (threadIdx.x == 0) sred[0] = x;
    }
    __syncthreads();
    v = sred[0];
    __syncthreads();
    return v;
}

__global__ __launch_bounds__(256) void rowstats_kernel(const float* __restrict__ thrs)
{
    __shared__ float buf[SS];
    __shared__ float sred[8];
    const int row = blockIdx.x;
    const int h = (row >> 11) & (HH - 1);
    const float thr = thrs[h];
    const float* Lrow = g_L + (size_t)row * SS;
    const int tid = threadIdx.x;

    float4* b4 = (float4*)buf;
    const float4* l4 = (const float4*)Lrow;
    #pragma unroll
    for (int i = tid; i < SS / 4; i += 256) b4[i] = l4[i];
    __syncthreads();

    float mx = -3.4e38f;
    #pragma unroll
    for (int i = tid; i < SS; i += 256) mx = fmaxf(mx, buf[i]);
    const float m = block_reduce_max(mx, sred);

    float z = 0.f;
    #pragma unroll
    for (int i = tid; i < SS; i += 256) z += __expf(buf[i] - m);
    const float Z1 = block_reduce_sum(z, sred);

    const float tz = thr * Z1;
    if (tz >= 1.0f) {
        if (tid == 0) {
            float4 st; st.x = 0.f; st.y = __int_as_float(0x7f800000);
            st.z = 0.f; st.w = 1.0f / (float)SS;
            g_stats[row] = st;
        }
        return;
    }
    const float cut = m + logf(tz);
    float z2 = 0.f;
    #pragma unroll
    for (int i = tid; i < SS; i += 256) {
        const float l = buf[i];
        if (l > cut) z2 += __expf(l - m);
    }
    const float Z2 = block_reduce_sum(z2, sred);
    if (tid == 0) {
        float4 st; st.x = m; st.y = cut; st.z = 1.0f / Z2; st.w = 0.f;
        g_stats[row] = st;
    }
}

// ===========================================================================
// Kernel 3b: V transpose + hi/lo split: g_Vhi/g_Vlo [bh][hd][s]
// ===========================================================================
__global__ __launch_bounds__(256) void vsplit_kernel()
{
    __shared__ float t[64][132];
    const int bh = blockIdx.y, s0 = blockIdx.x * 128;
    const float* Vb = g_V + (size_t)bh * SS * HD;
    const int sl = threadIdx.x >> 1;
    const int hh = (threadIdx.x & 1) * 32;
    #pragma unroll
    for (int j = 0; j < 8; ++j) {
        float4 v = *(const float4*)(Vb + (size_t)(s0 + sl) * HD + hh + j * 4);
        t[hh + j*4 + 0][sl] = v.x; t[hh + j*4 + 1][sl] = v.y;
        t[hh + j*4 + 2][sl] = v.z; t[hh + j*4 + 3][sl] = v.w;
    }
    __syncthreads();
    const int row = threadIdx.x >> 2;
    const int q = (threadIdx.x & 3) * 32;
    const size_t base = ((size_t)bh * HD + row) * SS + s0 + q;
    #pragma unroll
    for (int g = 0; g < 4; ++g) {
        const float* src = &t[row][q + g * 8];
        uint16_t h[8], l[8];
        #pragma unroll
        for (int j = 0; j < 8; ++j) split_bf(src[j], h[j], l[j]);
        uint4 oh, ol;
        oh.x = pack16(h[0],h[1]); oh.y = pack16(h[2],h[3]);
        oh.z = pack16(h[4],h[5]); oh.w = pack16(h[6],h[7]);
        ol.x = pack16(l[0],l[1]); ol.y = pack16(l[2],l[3]);
        ol.z = pack16(l[4],l[5]); ol.w = pack16(l[6],l[7]);
        *(uint4*)(g_Vhi + base + g * 8) = oh;
        *(uint4*)(g_Vlo + base + g * 8) = ol;
    }
}

// Kernel 3c: o_w -> split [hi|lo|hi] rows of 3072
__global__ __launch_bounds__(256) void owsplit_kernel(const float* __restrict__ ow)
{
    const int idx = blockIdx.x * 256 + threadIdx.x;   // group of 4 elems
    const int n = idx >> 8;
    const int k4 = (idx & 255) * 4;
    float4 v = *(const float4*)(ow + (size_t)n * DD + k4);
    uint16_t h[4], l[4];
    split_bf(v.x, h[0], l[0]); split_bf(v.y, h[1], l[1]);
    split_bf(v.z, h[2], l[2]); split_bf(v.w, h[3], l[3]);
    __nv_bfloat16* row = g_OWs + (size_t)n * E3D;
    *(uint2*)(row + k4)        = make_uint2(pack16(h[0],h[1]), pack16(h[2],h[3]));
    *(uint2*)(row + DD + k4)   = make_uint2(pack16(l[0],l[1]), pack16(l[2],l[3]));
    *(uint2*)(row + 2*DD + k4) = make_uint2(pack16(h[0],h[1]), pack16(h[2],h[3]));
}

// ===========================================================================
// Kernel 4: PV via mma.sync bf16 with 3-term split (whi*vhi + whi*vlo + wlo*vhi)
// Tile M=128(q) x N=64(hd), K chunks of 32 over S=2048. 256 thr = 8 warps (4x2).
// ===========================================================================
__global__ __launch_bounds__(256) void pv_mma_kernel()
{
    __shared__ __align__(16) __nv_bfloat16 sAhi[128 * TSTRIDE];
    __shared__ __align__(16) __nv_bfloat16 sAlo[128 * TSTRIDE];
    __shared__ __align__(16) __nv_bfloat16 sBhi[64 * TSTRIDE];
    __shared__ __align__(16) __nv_bfloat16 sBlo[64 * TSTRIDE];
    __shared__ float4 s_stats[128];

    const int tid = threadIdx.x;
    const int lane = tid & 31, wid = tid >> 5;
    const int wm = wid & 3, wn = wid >> 2;
    const int bh = blockIdx.y;
    const int q0 = blockIdx.x * 128;

    if (tid < 128) s_stats[tid] = g_stats[(size_t)bh * SS + q0 + tid];

    // fill mappings
    const int ar = tid >> 1;                 // L row 0..127
    const int ac = (tid & 1) * 16;           // col half
    const float* Lrow = g_L + ((size_t)bh * SS + q0 + ar) * SS + ac;
    const int vr = tid >> 2;                 // V row (hd) 0..63
    const int vc = (tid & 3) * 8;            // col group
    const __nv_bfloat16* Vhrow = g_Vhi + ((size_t)bh * HD + vr) * SS + vc;
    const __nv_bfloat16* Vlrow = g_Vlo + ((size_t)bh * HD + vr) * SS + vc;

    // ldmatrix lane addressing
    const uint32_t aHiB = smem_u32(sAhi), aLoB = smem_u32(sAlo);
    const uint32_t bHiB = smem_u32(sBhi), bLoB = smem_u32(sBlo);
    const int a_row = wm * 32 + ((lane >> 3) & 1) * 8 + (lane & 7);
    const int a_kadd = ((lane >> 4) & 1) * 8;
    const int b_row = wn * 32 + ((lane >> 4) & 1) * 8 + (lane & 7);
    const int b_kadd = ((lane >> 3) & 1) * 8;

    float acc[2][4][4];
    #pragma unroll
    for (int i = 0; i < 2; i++)
        #pragma unroll
        for (int j = 0; j < 4; j++)
            #pragma unroll
            for (int r = 0; r < 4; r++) acc[i][j][r] = 0.f;

    // prefetch chunk 0
    float4 lreg[4];
    uint4 vh, vl;
    #pragma unroll
    for (int j = 0; j < 4; ++j) lreg[j] = *(const float4*)(Lrow + j * 4);
    vh = *(const uint4*)Vhrow;
    vl = *(const uint4*)Vlrow;
    __syncthreads();   // stats visible
    const float4 st = s_stats[ar];

    for (int c = 0; c < 64; ++c) {
        __syncthreads();  // previous chunk's mma reads done
        // store A tiles (w transform + split)
        {
            const float* lv = (const float*)lreg;
            uint16_t hi16[16], lo16[16];
            #pragma unroll
            for (int j = 0; j < 16; ++j) {
                const float l = lv[j];
                const float w = (l > st.y) ? __expf(l - st.x) * st.z : st.w;
                split_bf(w, hi16[j], lo16[j]);
            }
            uint32_t off = (uint32_t)(ar * TSTRIDE + ac);
            uint4 u;
            u.x = pack16(hi16[0],hi16[1]);  u.y = pack16(hi16[2],hi16[3]);
            u.z = pack16(hi16[4],hi16[5]);  u.w = pack16(hi16[6],hi16[7]);
            *(uint4*)(sAhi + off) = u;
            u.x = pack16(hi16[8],hi16[9]);  u.y = pack16(hi16[10],hi16[11]);
            u.z = pack16(hi16[12],hi16[13]);u.w = pack16(hi16[14],hi16[15]);
            *(uint4*)(sAhi + off + 8) = u;
            u.x = pack16(lo16[0],lo16[1]);  u.y = pack16(lo16[2],lo16[3]);
            u.z = pack16(lo16[4],lo16[5]);  u.w = pack16(lo16[6],lo16[7]);
            *(uint4*)(sAlo + off) = u;
            u.x = pack16(lo16[8],lo16[9]);  u.y = pack16(lo16[10],lo16[11]);
            u.z = pack16(lo16[12],lo16[13]);u.w = pack16(lo16[14],lo16[15]);
            *(uint4*)(sAlo + off + 8) = u;
        }
        *(uint4*)(sBhi + vr * TSTRIDE + vc) = vh;
        *(uint4*)(sBlo + vr * TSTRIDE + vc) = vl;

        // prefetch next chunk
        if (c + 1 < 64) {
            #pragma unroll
            for (int j = 0; j < 4; ++j)
                lreg[j] = *(const float4*)(Lrow + (c + 1) * 32 + j * 4);
            vh = *(const uint4*)(Vhrow + (c + 1) * 32);
            vl = *(const uint4*)(Vlrow + (c + 1) * 32);
        }
        __syncthreads();

        // mma over this chunk: 2 ksteps x 3 products
        #pragma unroll
        for (int ks = 0; ks < 2; ++ks) {
            const int kc = ks * 16;
            uint32_t ah[2][4], al[2][4], bhf[2][4], blf[2][4];
            #pragma unroll
            for (int i = 0; i < 2; ++i) {
                uint32_t ro = (uint32_t)((a_row + i * 16) * TSTRIDE + kc + a_kadd) * 2;
                ldsm4(ah[i], aHiB + ro);
                ldsm4(al[i], aLoB + ro);
            }
            #pragma unroll
            for (int p = 0; p < 2; ++p) {
                uint32_t ro = (uint32_t)((b_row + p * 16) * TSTRIDE + kc + b_kadd) * 2;
                ldsm4(bhf[p], bHiB + ro);
                ldsm4(blf[p], bLoB + ro);
            }
            #pragma unroll
            for (int i = 0; i < 2; ++i)
                #pragma unroll
                for (int jn = 0; jn < 4; ++jn) {
                    const int p = jn >> 1, q = (jn & 1) * 2;
                    mma16816(acc[i][jn], ah[i], bhf[p][q], bhf[p][q + 1]);
                    mma16816(acc[i][jn], ah[i], blf[p][q], blf[p][q + 1]);
                    mma16816(acc[i][jn], al[i], bhf[p][q], bhf[p][q + 1]);
                }
        }
    }

    // epilogue: split accum -> g_valsS rows [hi|hi|lo]
    const int b = bh >> 4, h = bh & (HH - 1);
    const int g = lane >> 2, t = lane & 3;
    #pragma unroll
    for (int i = 0; i < 2; ++i) {
        #pragma unroll
        for (int jn = 0; jn < 4; ++jn) {
            const int n = wn * 32 + jn * 8 + 2 * t;   // hd col (even)
            #pragma unroll
            for (int half = 0; half < 2; ++half) {
                const int q = q0 + wm * 32 + i * 16 + g + half * 8;
                const float x0 = acc[i][jn][half * 2 + 0];
                const float x1 = acc[i][jn][half * 2 + 1];
                uint16_t h0, l0, h1, l1;
                split_bf(x0, h0, l0);
                split_bf(x1, h1, l1);
                __nv_bfloat16* rowp = g_valsS + (size_t)(b * SS + q) * E3D + h * HD + n;
                *(uint32_t*)(rowp)          = pack16(h0, h1);
                *(uint32_t*)(rowp + DD)     = pack16(h0, h1);
                *(uint32_t*)(rowp + 2 * DD) = pack16(l0, l1);
            }
        }
    }
}

// ===========================================================================
// Kernel 5: O projection via mma.sync bf16, K=3072 concat split.
// out[m][n] = sum_k valsS[m][k]*OWs[n][k] + ob[n]
// ===========================================================================
__global__ __launch_bounds__(256) void oproj_mma_kernel(
    const float* __restrict__ ob, float* __restrict__ out)
{
    __shared__ __align__(16) __nv_bfloat16 sA[128 * TSTRIDE];
    __shared__ __align__(16) __nv_bfloat16 sB[64 * TSTRIDE];

    const int tid = threadIdx.x;
    const int lane = tid & 31, wid = tid >> 5;
    const int wm = wid & 3, wn = wid >> 2;
    const int m0 = blockIdx.x * 128;
    const int n0 = blockIdx.y * 64;

    const int ar = tid >> 1;
    const int ac = (tid & 1) * 16;
    const __nv_bfloat16* Arow = g_valsS + (size_t)(m0 + ar) * E3D + ac;
    const int vr = tid >> 2;
    const int vc = (tid & 3) * 8;
    const __nv_bfloat16* Brow = g_OWs + (size_t)(n0 + vr) * E3D + vc;

    const uint32_t aB = smem_u32(sA), bB = smem_u32(sB);
    const int a_row = wm * 32 + ((lane >> 3) & 1) * 8 + (lane & 7);
    const int a_kadd = ((lane >> 4) & 1) * 8;
    const int b_row = wn * 32 + ((lane >> 4) & 1) * 8 + (lane & 7);
    const int b_kadd = ((lane >> 3) & 1) * 8;

    float acc[2][4][4];
    #pragma unroll
    for (int i = 0; i < 2; i++)
        #pragma unroll
        for (int j = 0; j < 4; j++)
            #pragma unroll
            for (int r = 0; r < 4; r++) acc[i][j][r] = 0.f;

    uint4 a0, a1, b0;
    a0 = *(const uint4*)(Arow);
    a1 = *(const uint4*)(Arow + 8);
    b0 = *(const uint4*)(Brow);

    const int NCH = E3D / 32;   // 96
    for (int c = 0; c < NCH; ++c) {
        __syncthreads();
        *(uint4*)(sA + ar * TSTRIDE + ac) = a0;
        *(uint4*)(sA + ar * TSTRIDE + ac + 8) = a1;
        *(uint4*)(sB + vr * TSTRIDE + vc) = b0;
        if (c + 1 < NCH) {
            a0 = *(const uint4*)(Arow + (c + 1) * 32);
            a1 = *(const uint4*)(Arow + (c + 1) * 32 + 8);
            b0 = *(const uint4*)(Brow + (c + 1) * 32);
        }
        __syncthreads();

        #pragma unroll
        for (int ks = 0; ks < 2; ++ks) {
            const int kc = ks * 16;
            uint32_t af[2][4], bf[2][4];
            #pragma unroll
            for (int i = 0; i < 2; ++i)
                ldsm4(af[i], aB + (uint32_t)((a_row + i * 16) * TSTRIDE + kc + a_kadd) * 2);
            #pragma unroll
            for (int p = 0; p < 2; ++p)
                ldsm4(bf[p], bB + (uint32_t)((b_row + p * 16) * TSTRIDE + kc + b_kadd) * 2);
            #pragma unroll
            for (int i = 0; i < 2; ++i)
                #pragma unroll
                for (int jn = 0; jn < 4; ++jn) {
                    const int p = jn >> 1, q = (jn & 1) * 2;
                    mma16816(acc[i][jn], af[i], bf[p][q], bf[p][q + 1]);
                }
        }
    }

    const int g = lane >> 2, t = lane & 3;
    #pragma unroll
    for (int i = 0; i < 2; ++i) {
        #pragma unroll
        for (int jn = 0; jn < 4; ++jn) {
            const int n = n0 + wn * 32 + jn * 8 + 2 * t;
            const float bx = ob[n], by = ob[n + 1];
            #pragma unroll
            for (int half = 0; half < 2; ++half) {
                const int m = m0 + wm * 32 + i * 16 + g + half * 8;
                float2 v;
                v.x = acc[i][jn][half * 2 + 0] + bx;
                v.y = acc[i][jn][half * 2 + 1] + by;
                *(float2*)(out + (size_t)m * DD + n) = v;
            }
        }
    }
}

// ===========================================================================
extern "C" void kernel_launch(void* const* d_in, const int* in_sizes, int n_in,
                              void* d_out, int out_size)
{
    const float *x = nullptr, *thr = nullptr, *qkvw = nullptr,
                *qkvb = nullptr, *ow = nullptr, *ob = nullptr;
    for (int i = 0; i < n_in; ++i) {
        const float* p = (const float*)d_in[i];
        switch (in_sizes[i]) {
            case MROWS * DD:   x = p;    break;
            case HH:           thr = p;  break;
            case E3D * DD:     qkvw = p; break;
            case E3D:          qkvb = p; break;
            case DD * DD:      ow = p;   break;
            case DD:           ob = p;   break;
        }
    }
    float* out = (float*)d_out;

    qkv_gemm_kernel<<<dim3(MROWS / 128, E3D / 128), 256>>>(x, qkvw, qkvb);
    vsplit_kernel<<<dim3(SS / 128, BH), 256>>>();
    owsplit_kernel<<<(DD * DD) / (256 * 4), 256>>>(ow);
    logits_kernel<<<dim3(SS / 128, SS / 128, BH), 256>>>();
    rowstats_kernel<<<BH * SS, 256>>>(thr);
    pv_mma_kernel<<<dim3(SS / 128, BH), 256>>>();
    oproj_mma_kernel<<<dim3(MROWS / 128, DD / 64), 256>>>(ob, out);
}

// round 6
// speedup vs baseline: 1.3619x; 1.1256x over previous
#include <cuda_runtime.h>
#include <cuda_bf16.h>
#include <cuda_fp16.h>
#include <cstdint>

// Problem constants
#define BB 2
#define SS 2048
#define DD 1024
#define HH 16
#define HD 64
#define BH (BB*HH)          // 32
#define MROWS (BB*SS)       // 4096
#define E3D (3*DD)          // 3072

// Scratch (device globals; allocation-free kernel_launch)
__device__ float g_V[(size_t)BH * SS * HD];            // 16 MB
__device__ float g_L[(size_t)BH * SS * SS];            // 512 MB
__device__ float4 g_stats[(size_t)BH * SS];            // {m, cut, invZ2, u}
__device__ __half g_Xh[(size_t)MROWS * DD];            // x 3-term split
__device__ __half g_Xm[(size_t)MROWS * DD];
__device__ __half g_Xl[(size_t)MROWS * DD];
__device__ __half g_Wh[(size_t)E3D * DD];              // qkv_w 3-term split
__device__ __half g_Wm[(size_t)E3D * DD];
__device__ __half g_Wl[(size_t)E3D * DD];
__device__ __half g_Qh[(size_t)BH * SS * HD];          // Q 3-term [bh][s][hd]
__device__ __half g_Qm[(size_t)BH * SS * HD];
__device__ __half g_Ql[(size_t)BH * SS * HD];
__device__ __half g_Kh[(size_t)BH * SS * HD];          // K 3-term
__device__ __half g_Km[(size_t)BH * SS * HD];
__device__ __half g_Kl[(size_t)BH * SS * HD];
__device__ __nv_bfloat16 g_Vhi[(size_t)BH * HD * SS];  // V^T hi [bh][hd][s]
__device__ __nv_bfloat16 g_Vlo[(size_t)BH * HD * SS];  // V^T lo
__device__ __nv_bfloat16 g_valsS[(size_t)MROWS * E3D]; // vals split [hi|hi|lo]
__device__ __nv_bfloat16 g_OWs[(size_t)DD * E3D];      // o_w split  [hi|lo|hi]

#define C_G1 2.44140625e-4f            // 2^-12
#define C_G2 5.9604644775390625e-8f    // 2^-24

// ===========================================================================
// Helpers
// ===========================================================================
__device__ __forceinline__ uint32_t smem_u32(const void* p) {
    uint32_t a;
    asm("{ .reg .u64 t; cvta.to.shared.u64 t, %1; cvt.u32.u64 %0, t; }" : "=r"(a) : "l"(p));
    return a;
}
__device__ __forceinline__ uint32_t pack16(uint16_t a, uint16_t b) {
    return (uint32_t)a | ((uint32_t)b << 16);
}
__device__ __forceinline__ void split_bf(float x, uint16_t& h, uint16_t& l) {
    __nv_bfloat16 hb = __float2bfloat16(x);
    float r = x - __bfloat162float(hb);
    __nv_bfloat16 lb = __float2bfloat16(r);
    h = *reinterpret_cast<uint16_t*>(&hb);
    l = *reinterpret_cast<uint16_t*>(&lb);
}
// scaled 3-term fp16 split: x = h + m*2^-12 + l*2^-24 (+O(x*2^-35))
__device__ __forceinline__ void split3(float x, uint16_t& h, uint16_t& m, uint16_t& l) {
    __half a = __float2half_rn(x);
    float r1 = x - __half2float(a);
    __half b = __float2half_rn(r1 * 4096.0f);
    float r2 = r1 - __half2float(b) * C_G1;
    __half c = __float2half_rn(r2 * 16777216.0f);
    h = *reinterpret_cast<uint16_t*>(&a);
    m = *reinterpret_cast<uint16_t*>(&b);
    l = *reinterpret_cast<uint16_t*>(&c);
}
__device__ __forceinline__ void ldsm4(uint32_t* r, uint32_t addr) {
    asm volatile("ldmatrix.sync.aligned.m8n8.x4.shared.b16 {%0,%1,%2,%3}, [%4];"
                 : "=r"(r[0]), "=r"(r[1]), "=r"(r[2]), "=r"(r[3]) : "r"(addr));
}
__device__ __forceinline__ void mma16816(float* c, const uint32_t* a,
                                         uint32_t b0, uint32_t b1) {
    asm volatile(
        "mma.sync.aligned.m16n8k16.row.col.f32.bf16.bf16.f32 "
        "{%0,%1,%2,%3}, {%4,%5,%6,%7}, {%8,%9}, {%0,%1,%2,%3};"
        : "+f"(c[0]), "+f"(c[1]), "+f"(c[2]), "+f"(c[3])
        : "r"(a[0]), "r"(a[1]), "r"(a[2]), "r"(a[3]), "r"(b0), "r"(b1));
}
__device__ __forceinline__ void mma16816h(float* c, const uint32_t* a,
                                          uint32_t b0, uint32_t b1) {
    asm volatile(
        "mma.sync.aligned.m16n8k16.row.col.f32.f16.f16.f32 "
        "{%0,%1,%2,%3}, {%4,%5,%6,%7}, {%8,%9}, {%0,%1,%2,%3};"
        : "+f"(c[0]), "+f"(c[1]), "+f"(c[2]), "+f"(c[3])
        : "r"(a[0]), "r"(a[1]), "r"(a[2]), "r"(a[3]), "r"(b0), "r"(b1));
}
__device__ __forceinline__ void cp16(uint32_t dst, const void* src) {
    asm volatile("cp.async.cg.shared.global [%0], [%1], 16;" :: "r"(dst), "l"(src));
}
#define CP_COMMIT() asm volatile("cp.async.commit_group;")
#define CP_WAIT1()  asm volatile("cp.async.wait_group 1;")
#define CP_WAIT0()  asm volatile("cp.async.wait_group 0;")

#define TSTRIDE 40   // 16-bit elems per smem row for chunked tiles (80B)
#define LSTRIDE 72   // 16-bit elems per smem row for full-K logits tiles (144B)

// ===========================================================================
// Kernel 0: fp32 -> scaled 3-term fp16 split. 4 elems/thread.
// ===========================================================================
__global__ __launch_bounds__(256) void split3_kernel(
    const float* __restrict__ src, __half* __restrict__ dh,
    __half* __restrict__ dm, __half* __restrict__ dl)
{
    const int i = blockIdx.x * 256 + threadIdx.x;
    float4 v = ((const float4*)src)[i];
    uint16_t h[4], m[4], l[4];
    split3(v.x, h[0], m[0], l[0]); split3(v.y, h[1], m[1], l[1]);
    split3(v.z, h[2], m[2], l[2]); split3(v.w, h[3], m[3], l[3]);
    ((uint2*)dh)[i] = make_uint2(pack16(h[0],h[1]), pack16(h[2],h[3]));
    ((uint2*)dm)[i] = make_uint2(pack16(m[0],m[1]), pack16(m[2],m[3]));
    ((uint2*)dl)[i] = make_uint2(pack16(l[0],l[1]), pack16(l[2],l[3]));
}

// ===========================================================================
// Kernel 1: QKV projection via 3-term fp16 HMMA (6 products; V blocks: 3).
// Tile M=128 x N=64, K chunks of 32 (K=1024), cp.async double-buffered.
// G0 (hh) accumulator is DRAINED into an fp32 RN accumulator every chunk to
// bound the tensor-core round-toward-zero accumulation bias (chain length 2).
// ===========================================================================
#define QKV_BUF 46080
#define QKV_SMEM (2*QKV_BUF)
__global__ __launch_bounds__(256) void qkv_mma_kernel(const float* __restrict__ bias)
{
    extern __shared__ __align__(16) char qsm[];
    const int tid = threadIdx.x;
    const int lane = tid & 31, wid = tid >> 5;
    const int wm = wid & 3, wn = wid >> 2;
    const int m0 = blockIdx.x * 128;
    const int e0 = blockIdx.y * 64;
    const int typ = (e0 >> 6) % 3;          // 0=Q, 1=K, 2=V
    const bool vmode = (typ == 2);
    const int head = e0 / 192;

    const uint32_t sb0 = smem_u32(qsm);
    const int rA = tid >> 1;
    const int gA = (tid & 1) * 2;
    const int rB = tid >> 2;
    const int gB = tid & 3;

    const __half* XA[3] = { g_Xh, g_Xm, g_Xl };
    const __half* WB[3] = { g_Wh, g_Wm, g_Wl };
    const uint32_t Aoff[3] = { 0u, 10240u, 20480u };
    const uint32_t Boff[3] = { 30720u, 35840u, 40960u };
    const int nTiles = vmode ? 2 : 3;

    const int a_row = wm * 32 + ((lane >> 3) & 1) * 8 + (lane & 7);
    const int a_kadd = ((lane >> 4) & 1) * 8;
    const int b_row = wn * 32 + ((lane >> 4) & 1) * 8 + (lane & 7);
    const int b_kadd = ((lane >> 3) & 1) * 8;

    float acc0[2][4][4], acc1[2][4][4], acc2[2][4][4], gr0[2][4][4];
    #pragma unroll
    for (int i = 0; i < 2; i++)
        #pragma unroll
        for (int j = 0; j < 4; j++)
            #pragma unroll
            for (int r = 0; r < 4; r++) {
                acc0[i][j][r]=0.f; acc1[i][j][r]=0.f; acc2[i][j][r]=0.f; gr0[i][j][r]=0.f;
            }

    auto issue = [&](int c, int bb) {
        const uint32_t sb = sb0 + bb * QKV_BUF;
        #pragma unroll
        for (int T = 0; T < 3; ++T) {
            if (T >= nTiles) break;
            const __half* srcA = XA[T] + (size_t)(m0 + rA) * DD + c * 32 + gA * 8;
            uint32_t dstA = sb + Aoff[T] + (uint32_t)(rA * TSTRIDE + gA * 8) * 2;
            cp16(dstA, srcA);
            cp16(dstA + 16, srcA + 8);
            const __half* srcB = WB[T] + (size_t)(e0 + rB) * DD + c * 32 + gB * 8;
            uint32_t dstB = sb + Boff[T] + (uint32_t)(rB * TSTRIDE + gB * 8) * 2;
            cp16(dstB, srcB);
        }
        CP_COMMIT();
    };

    issue(0, 0);
    const int NCH = DD / 32;   // 32
    for (int c = 0; c < NCH; ++c) {
        if (c + 1 < NCH) { issue(c + 1, (c + 1) & 1); CP_WAIT1(); }
        else             { CP_WAIT0(); }
        __syncthreads();

        const uint32_t sb = sb0 + (c & 1) * QKV_BUF;
        #pragma unroll
        for (int ks = 0; ks < 2; ++ks) {
            const int kc = ks * 16;
            uint32_t fah[2][4], fam[2][4], fal[2][4];
            uint32_t fbh[2][4], fbm[2][4], fbl[2][4];
            #pragma unroll
            for (int i = 0; i < 2; ++i) {
                uint32_t ro = (uint32_t)((a_row + i * 16) * TSTRIDE + kc + a_kadd) * 2;
                ldsm4(fah[i], sb + Aoff[0] + ro);
                ldsm4(fam[i], sb + Aoff[1] + ro);
                if (!vmode) ldsm4(fal[i], sb + Aoff[2] + ro);
            }
            #pragma unroll
            for (int p = 0; p < 2; ++p) {
                uint32_t ro = (uint32_t)((b_row + p * 16) * TSTRIDE + kc + b_kadd) * 2;
                ldsm4(fbh[p], sb + Boff[0] + ro);
                ldsm4(fbm[p], sb + Boff[1] + ro);
                if (!vmode) ldsm4(fbl[p], sb + Boff[2] + ro);
            }
            #pragma unroll
            for (int i = 0; i < 2; ++i)
                #pragma unroll
                for (int jn = 0; jn < 4; ++jn) {
                    const int p = jn >> 1, q = (jn & 1) * 2;
                    mma16816h(acc0[i][jn], fah[i], fbh[p][q], fbh[p][q + 1]);
                    mma16816h(acc1[i][jn], fah[i], fbm[p][q], fbm[p][q + 1]);
                    mma16816h(acc1[i][jn], fam[i], fbh[p][q], fbh[p][q + 1]);
                    if (!vmode) {
                        mma16816h(acc2[i][jn], fah[i], fbl[p][q], fbl[p][q + 1]);
                        mma16816h(acc2[i][jn], fam[i], fbm[p][q], fbm[p][q + 1]);
                        mma16816h(acc2[i][jn], fal[i], fbh[p][q], fbh[p][q + 1]);
                    }
                }
        }
        // drain G0 (RZ chain length 2) into RN grand accumulator
        #pragma unroll
        for (int i = 0; i < 2; ++i)
            #pragma unroll
            for (int jn = 0; jn < 4; ++jn)
                #pragma unroll
                for (int r = 0; r < 4; ++r) {
                    gr0[i][jn][r] += acc0[i][jn][r];
                    acc0[i][jn][r] = 0.f;
                }
        __syncthreads();
    }

    // epilogue
    const int g = lane >> 2, t = lane & 3;
    #pragma unroll
    for (int i = 0; i < 2; ++i) {
        #pragma unroll
        for (int jn = 0; jn < 4; ++jn) {
            const int nn = wn * 32 + jn * 8 + 2 * t;     // hd (even)
            const int e = e0 + nn;
            const float be0 = bias[e], be1 = bias[e + 1];
            #pragma unroll
            for (int half = 0; half < 2; ++half) {
                const int m = m0 + wm * 32 + i * 16 + g + half * 8;
                const int r0 = half * 2, r1 = half * 2 + 1;
                const float x0 = gr0[i][jn][r0] + C_G1 * acc1[i][jn][r0] + C_G2 * acc2[i][jn][r0] + be0;
                const float x1 = gr0[i][jn][r1] + C_G1 * acc1[i][jn][r1] + C_G2 * acc2[i][jn][r1] + be1;
                const int b = m >> 11, s = m & (SS - 1);
                const size_t base = (((size_t)(b * HH + head) * SS) + s) * HD + nn;
                if (typ == 0) {
                    uint16_t h0,m0_,l0,h1,m1,l1;
                    split3(x0, h0, m0_, l0); split3(x1, h1, m1, l1);
                    *(uint32_t*)(g_Qh + base) = pack16(h0, h1);
                    *(uint32_t*)(g_Qm + base) = pack16(m0_, m1);
                    *(uint32_t*)(g_Ql + base) = pack16(l0, l1);
                } else if (typ == 1) {
                    uint16_t h0,m0_,l0,h1,m1,l1;
                    split3(x0, h0, m0_, l0); split3(x1, h1, m1, l1);
                    *(uint32_t*)(g_Kh + base) = pack16(h0, h1);
                    *(uint32_t*)(g_Km + base) = pack16(m0_, m1);
                    *(uint32_t*)(g_Kl + base) = pack16(l0, l1);
                } else {
                    *(float2*)(g_V + base) = make_float2(x0, x1);
                }
            }
        }
    }
}

// ===========================================================================
// Kernel 2: logits via 3-term fp16 HMMA (6 products).
// Tile M=128(q) x N=64(k-seq), full K=64 resident. G0 drained EVERY kstep
// (RZ chain length 1: each mma is a pure 16-dot, RN-summed in registers).
// ===========================================================================
#define LG_SMEM 82944
__global__ __launch_bounds__(256) void logits_mma_kernel()
{
    extern __shared__ __align__(16) char lsm[];
    const int tid = threadIdx.x;
    const int lane = tid & 31, wid = tid >> 5;
    const int wm = wid & 3, wn = wid >> 2;
    const int bh = blockIdx.z;
    const int q0 = blockIdx.x * 128;
    const int n0 = blockIdx.y * 64;

    const uint32_t sb = smem_u32(lsm);
    const uint32_t Aoff[3] = { 0u, 18432u, 36864u };
    const uint32_t Boff[3] = { 55296u, 64512u, 73728u };
    const __half* QA[3] = { g_Qh, g_Qm, g_Ql };
    const __half* KB[3] = { g_Kh, g_Km, g_Kl };

    #pragma unroll
    for (int it = 0; it < 4; ++it) {
        const int idx = tid + it * 256;          // 0..1023
        const int r = idx >> 3, gg = idx & 7;
        #pragma unroll
        for (int T = 0; T < 3; ++T)
            cp16(sb + Aoff[T] + (uint32_t)(r * LSTRIDE + gg * 8) * 2,
                 QA[T] + ((size_t)bh * SS + q0 + r) * HD + gg * 8);
    }
    #pragma unroll
    for (int it = 0; it < 2; ++it) {
        const int idx = tid + it * 256;          // 0..511
        const int r = idx >> 3, gg = idx & 7;
        #pragma unroll
        for (int T = 0; T < 3; ++T)
            cp16(sb + Boff[T] + (uint32_t)(r * LSTRIDE + gg * 8) * 2,
                 KB[T] + ((size_t)bh * SS + n0 + r) * HD + gg * 8);
    }
    CP_COMMIT();
    CP_WAIT0();
    __syncthreads();

    const int a_row = wm * 32 + ((lane >> 3) & 1) * 8 + (lane & 7);
    const int a_kadd = ((lane >> 4) & 1) * 8;
    const int b_row = wn * 32 + ((lane >> 4) & 1) * 8 + (lane & 7);
    const int b_kadd = ((lane >> 3) & 1) * 8;

    float acc0[2][4][4], acc1[2][4][4], acc2[2][4][4], gr0[2][4][4];
    #pragma unroll
    for (int i = 0; i < 2; i++)
        #pragma unroll
        for (int j = 0; j < 4; j++)
            #pragma unroll
            for (int r = 0; r < 4; r++) {
                acc0[i][j][r]=0.f; acc1[i][j][r]=0.f; acc2[i][j][r]=0.f; gr0[i][j][r]=0.f;
            }

    #pragma unroll
    for (int ks = 0; ks < 4; ++ks) {
        const int kc = ks * 16;
        uint32_t fah[2][4], fam[2][4], fal[2][4];
        uint32_t fbh[2][4], fbm[2][4], fbl[2][4];
        #pragma unroll
        for (int i = 0; i < 2; ++i) {
            uint32_t ro = (uint32_t)((a_row + i * 16) * LSTRIDE + kc + a_kadd) * 2;
            ldsm4(fah[i], sb + Aoff[0] + ro);
            ldsm4(fam[i], sb + Aoff[1] + ro);
            ldsm4(fal[i], sb + Aoff[2] + ro);
        }
        #pragma unroll
        for (int p = 0; p < 2; ++p) {
            uint32_t ro = (uint32_t)((b_row + p * 16) * LSTRIDE + kc + b_kadd) * 2;
            ldsm4(fbh[p], sb + Boff[0] + ro);
            ldsm4(fbm[p], sb + Boff[1] + ro);
            ldsm4(fbl[p], sb + Boff[2] + ro);
        }
        #pragma unroll
        for (int i = 0; i < 2; ++i)
            #pragma unroll
            for (int jn = 0; jn < 4; ++jn) {
                const int p = jn >> 1, q = (jn & 1) * 2;
                mma16816h(acc0[i][jn], fah[i], fbh[p][q], fbh[p][q + 1]);
                mma16816h(acc1[i][jn], fah[i], fbm[p][q], fbm[p][q + 1]);
                mma16816h(acc1[i][jn], fam[i], fbh[p][q], fbh[p][q + 1]);
                mma16816h(acc2[i][jn], fah[i], fbl[p][q], fbl[p][q + 1]);
                mma16816h(acc2[i][jn], fam[i], fbm[p][q], fbm[p][q + 1]);
                mma16816h(acc2[i][jn], fal[i], fbh[p][q], fbh[p][q + 1]);
            }
        // drain G0 every kstep (RZ chain length 1)
        #pragma unroll
        for (int i = 0; i < 2; ++i)
            #pragma unroll
            for (int jn = 0; jn < 4; ++jn)
                #pragma unroll
                for (int r = 0; r < 4; ++r) {
                    gr0[i][jn][r] += acc0[i][jn][r];
                    acc0[i][jn][r] = 0.f;
                }
    }

    float* Lb = g_L + (size_t)bh * SS * SS;
    const int g = lane >> 2, t = lane & 3;
    #pragma unroll
    for (int i = 0; i < 2; ++i) {
        #pragma unroll
        for (int jn = 0; jn < 4; ++jn) {
            const int n = n0 + wn * 32 + jn * 8 + 2 * t;
            #pragma unroll
            for (int half = 0; half < 2; ++half) {
                const int q = q0 + wm * 32 + i * 16 + g + half * 8;
                const int r0 = half * 2, r1 = half * 2 + 1;
                float2 v;
                v.x = (gr0[i][jn][r0] + C_G1 * acc1[i][jn][r0] + C_G2 * acc2[i][jn][r0]) * 0.125f;
                v.y = (gr0[i][jn][r1] + C_G1 * acc1[i][jn][r1] + C_G2 * acc2[i][jn][r1]) * 0.125f;
                *(float2*)(Lb + (size_t)q * SS + n) = v;
            }
        }
    }
}

// ===========================================================================
// Kernel 3: per-row softmax stats -> {m, cut, invZ2, u}
// ===========================================================================
__device__ __forceinline__ float block_reduce_max(float v, float* sred) {
    #pragma unroll
    for (int o = 16; o > 0; o >>= 1) v = fmaxf(v, __shfl_xor_sync(0xffffffffu, v, o));
    const int w = threadIdx.x >> 5;
    if ((threadIdx.x & 31) == 0) sred[w] = v;
    __syncthreads();
    if (threadIdx.x < 32) {
        float x = (threadIdx.x < 8) ? sred[threadIdx.x] : -3.4e38f;
        #pragma unroll
        for (int o = 4; o > 0; o >>= 1) x = fmaxf(x, __shfl_xor_sync(0xffffffffu, x, o));
        if (threadIdx.x == 0) sred[0] = x;
    }
    __syncthreads();
    v = sred[0];
    __syncthreads();
    return v;
}
__device__ __forceinline__ float block_reduce_sum(float v, float* sred) {
    #pragma unroll
    for (int o = 16; o > 0; o >>= 1) v += __shfl_xor_sync(0xffffffffu, v, o);
    const int w = threadIdx.x >> 5;
    if ((threadIdx.x & 31) == 0) sred[w] = v;
    __syncthreads();
    if (threadIdx.x < 32) {
        float x = (threadIdx.x < 8) ? sred[threadIdx.x] : 0.f;
        #pragma unroll
        for (int o = 4; o > 0; o >>= 1) x += __shfl_xor_sync(0xffffffffu, x, o);
        if (threadIdx.x == 0) sred[0] = x;
    }
    __syncthreads();
    v = sred[0];
    __syncthreads();
    return v;
}

__global__ __launch_bounds__(256) void rowstats_kernel(const float* __restrict__ thrs)
{
    __shared__ float buf[SS];
    __shared__ float sred[8];
    const int row = blockIdx.x;
    const int h = (row >> 11) & (HH - 1);
    const float thr = thrs[h];
    const float* Lrow = g_L + (size_t)row * SS;
    const int tid = threadIdx.x;

    float4* b4 = (float4*)buf;
    const float4* l4 = (const float4*)Lrow;
    #pragma unroll
    for (int i = tid; i < SS / 4; i += 256) b4[i] = l4[i];
    __syncthreads();

    float mx = -3.4e38f;
    #pragma unroll
    for (int i = tid; i < SS; i += 256) mx = fmaxf(mx, buf[i]);
    const float m = block_reduce_max(mx, sred);

    float z = 0.f;
    #pragma unroll
    for (int i = tid; i < SS; i += 256) z += __expf(buf[i] - m);
    const float Z1 = block_reduce_sum(z, sred);

    const float tz = thr * Z1;
    if (tz >= 1.0f) {
        if (tid == 0) {
            float4 st; st.x = 0.f; st.y = __int_as_float(0x7f800000);
            st.z = 0.f; st.w = 1.0f / (float)SS;
            g_stats[row] = st;
        }
        return;
    }
    const float cut = m + logf(tz);
    float z2 = 0.f;
    #pragma unroll
    for (int i = tid; i < SS; i += 256) {
        const float l = buf[i];
        if (l > cut) z2 += __expf(l - m);
    }
    const float Z2 = block_reduce_sum(z2, sred);
    if (tid == 0) {
        float4 st; st.x = m; st.y = cut; st.z = 1.0f / Z2; st.w = 0.f;
        g_stats[row] = st;
    }
}

// ===========================================================================
// Kernel 3b: V transpose + bf16 hi/lo split: g_Vhi/g_Vlo [bh][hd][s]
// ===========================================================================
__global__ __launch_bounds__(256) void vsplit_kernel()
{
    __shared__ float t[64][132];
    const int bh = blockIdx.y, s0 = blockIdx.x * 128;
    const float* Vb = g_V + (size_t)bh * SS * HD;
    const int sl = threadIdx.x >> 1;
    const int hh = (threadIdx.x & 1) * 32;
    #pragma unroll
    for (int j = 0; j < 8; ++j) {
        float4 v = *(const float4*)(Vb + (size_t)(s0 + sl) * HD + hh + j * 4);
        t[hh + j*4 + 0][sl] = v.x; t[hh + j*4 + 1][sl] = v.y;
        t[hh + j*4 + 2][sl] = v.z; t[hh + j*4 + 3][sl] = v.w;
    }
    __syncthreads();
    const int row = threadIdx.x >> 2;
    const int q = (threadIdx.x & 3) * 32;
    const size_t base = ((size_t)bh * HD + row) * SS + s0 + q;
    #pragma unroll
    for (int g = 0; g < 4; ++g) {
        const float* src = &t[row][q + g * 8];
        uint16_t h[8], l[8];
        #pragma unroll
        for (int j = 0; j < 8; ++j) split_bf(src[j], h[j], l[j]);
        uint4 oh, ol;
        oh.x = pack16(h[0],h[1]); oh.y = pack16(h[2],h[3]);
        oh.z = pack16(h[4],h[5]); oh.w = pack16(h[6],h[7]);
        ol.x = pack16(l[0],l[1]); ol.y = pack16(l[2],l[3]);
        ol.z = pack16(l[4],l[5]); ol.w = pack16(l[6],l[7]);
        *(uint4*)(g_Vhi + base + g * 8) = oh;
        *(uint4*)(g_Vlo + base + g * 8) = ol;
    }
}

// Kernel 3c: o_w -> split [hi|lo|hi] rows of 3072
__global__ __launch_bounds__(256) void owsplit_kernel(const float* __restrict__ ow)
{
    const int idx = blockIdx.x * 256 + threadIdx.x;
    const int n = idx >> 8;
    const int k4 = (idx & 255) * 4;
    float4 v = *(const float4*)(ow + (size_t)n * DD + k4);
    uint16_t h[4], l[4];
    split_bf(v.x, h[0], l[0]); split_bf(v.y, h[1], l[1]);
    split_bf(v.z, h[2], l[2]); split_bf(v.w, h[3], l[3]);
    __nv_bfloat16* row = g_OWs + (size_t)n * E3D;
    *(uint2*)(row + k4)        = make_uint2(pack16(h[0],h[1]), pack16(h[2],h[3]));
    *(uint2*)(row + DD + k4)   = make_uint2(pack16(l[0],l[1]), pack16(l[2],l[3]));
    *(uint2*)(row + 2*DD + k4) = make_uint2(pack16(h[0],h[1]), pack16(h[2],h[3]));
}

// ===========================================================================
// Kernel 4: PV via mma.sync bf16, 3-term (whi*vhi + whi*vlo + wlo*vhi)
// ===========================================================================
__global__ __launch_bounds__(256) void pv_mma_kernel()
{
    __shared__ __align__(16) __nv_bfloat16 sAhi[128 * TSTRIDE];
    __shared__ __align__(16) __nv_bfloat16 sAlo[128 * TSTRIDE];
    __shared__ __align__(16) __nv_bfloat16 sBhi[64 * TSTRIDE];
    __shared__ __align__(16) __nv_bfloat16 sBlo[64 * TSTRIDE];
    __shared__ float4 s_stats[128];

    const int tid = threadIdx.x;
    const int lane = tid & 31, wid = tid >> 5;
    const int wm = wid & 3, wn = wid >> 2;
    const int bh = blockIdx.y;
    const int q0 = blockIdx.x * 128;

    if (tid < 128) s_stats[tid] = g_stats[(size_t)bh * SS + q0 + tid];

    const int ar = tid >> 1;
    const int ac = (tid & 1) * 16;
    const float* Lrow = g_L + ((size_t)bh * SS + q0 + ar) * SS + ac;
    const int vr = tid >> 2;
    const int vc = (tid & 3) * 8;
    const __nv_bfloat16* Vhrow = g_Vhi + ((size_t)bh * HD + vr) * SS + vc;
    const __nv_bfloat16* Vlrow = g_Vlo + ((size_t)bh * HD + vr) * SS + vc;

    const uint32_t aHiB = smem_u32(sAhi), aLoB = smem_u32(sAlo);
    const uint32_t bHiB = smem_u32(sBhi), bLoB = smem_u32(sBlo);
    const int a_row = wm * 32 + ((lane >> 3) & 1) * 8 + (lane & 7);
    const int a_kadd = ((lane >> 4) & 1) * 8;
    const int b_row = wn * 32 + ((lane >> 4) & 1) * 8 + (lane & 7);
    const int b_kadd = ((lane >> 3) & 1) * 8;

    float acc[2][4][4];
    #pragma unroll
    for (int i = 0; i < 2; i++)
        #pragma unroll
        for (int j = 0; j < 4; j++)
            #pragma unroll
            for (int r = 0; r < 4; r++) acc[i][j][r] = 0.f;

    float4 lreg[4];
    uint4 vh, vl;
    #pragma unroll
    for (int j = 0; j < 4; ++j) lreg[j] = *(const float4*)(Lrow + j * 4);
    vh = *(const uint4*)Vhrow;
    vl = *(const uint4*)Vlrow;
    __syncthreads();
    const float4 st = s_stats[ar];

    for (int c = 0; c < 64; ++c) {
        __syncthreads();
        {
            const float* lv = (const float*)lreg;
            uint16_t hi16[16], lo16[16];
            #pragma unroll
            for (int j = 0; j < 16; ++j) {
                const float l = lv[j];
                const float w = (l > st.y) ? __expf(l - st.x) * st.z : st.w;
                split_bf(w, hi16[j], lo16[j]);
            }
            uint32_t off = (uint32_t)(ar * TSTRIDE + ac);
            uint4 u;
            u.x = pack16(hi16[0],hi16[1]);  u.y = pack16(hi16[2],hi16[3]);
            u.z = pack16(hi16[4],hi16[5]);  u.w = pack16(hi16[6],hi16[7]);
            *(uint4*)(sAhi + off) = u;
            u.x = pack16(hi16[8],hi16[9]);  u.y = pack16(hi16[10],hi16[11]);
            u.z = pack16(hi16[12],hi16[13]);u.w = pack16(hi16[14],hi16[15]);
            *(uint4*)(sAhi + off + 8) = u;
            u.x = pack16(lo16[0],lo16[1]);  u.y = pack16(lo16[2],lo16[3]);
            u.z = pack16(lo16[4],lo16[5]);  u.w = pack16(lo16[6],lo16[7]);
            *(uint4*)(sAlo + off) = u;
            u.x = pack16(lo16[8],lo16[9]);  u.y = pack16(lo16[10],lo16[11]);
            u.z = pack16(lo16[12],lo16[13]);u.w = pack16(lo16[14],lo16[15]);
            *(uint4*)(sAlo + off + 8) = u;
        }
        *(uint4*)(sBhi + vr * TSTRIDE + vc) = vh;
        *(uint4*)(sBlo + vr * TSTRIDE + vc) = vl;

        if (c + 1 < 64) {
            #pragma unroll
            for (int j = 0; j < 4; ++j)
                lreg[j] = *(const float4*)(Lrow + (c + 1) * 32 + j * 4);
            vh = *(const uint4*)(Vhrow + (c + 1) * 32);
            vl = *(const uint4*)(Vlrow + (c + 1) * 32);
        }
        __syncthreads();

        #pragma unroll
        for (int ks = 0; ks < 2; ++ks) {
            const int kc = ks * 16;
            uint32_t ah[2][4], al[2][4], bhf[2][4], blf[2][4];
            #pragma unroll
            for (int i = 0; i < 2; ++i) {
                uint32_t ro = (uint32_t)((a_row + i * 16) * TSTRIDE + kc + a_kadd) * 2;
                ldsm4(ah[i], aHiB + ro);
                ldsm4(al[i], aLoB + ro);
            }
            #pragma unroll
            for (int p = 0; p < 2; ++p) {
                uint32_t ro = (uint32_t)((b_row + p * 16) * TSTRIDE + kc + b_kadd) * 2;
                ldsm4(bhf[p], bHiB + ro);
                ldsm4(blf[p], bLoB + ro);
            }
            #pragma unroll
            for (int i = 0; i < 2; ++i)
                #pragma unroll
                for (int jn = 0; jn < 4; ++jn) {
                    const int p = jn >> 1, q = (jn & 1) * 2;
                    mma16816(acc[i][jn], ah[i], bhf[p][q], bhf[p][q + 1]);
                    mma16816(acc[i][jn], ah[i], blf[p][q], blf[p][q + 1]);
                    mma16816(acc[i][jn], al[i], bhf[p][q], bhf[p][q + 1]);
                }
        }
    }

    const int b = bh >> 4, h = bh & (HH - 1);
    const int g = lane >> 2, t = lane & 3;
    #pragma unroll
    for (int i = 0; i < 2; ++i) {
        #pragma unroll
        for (int jn = 0; jn < 4; ++jn) {
            const int n = wn * 32 + jn * 8 + 2 * t;
            #pragma unroll
            for (int half = 0; half < 2; ++half) {
                const int q = q0 + wm * 32 + i * 16 + g + half * 8;
                const float x0 = acc[i][jn][half * 2 + 0];
                const float x1 = acc[i][jn][half * 2 + 1];
                uint16_t h0, l0, h1, l1;
                split_bf(x0, h0, l0);
                split_bf(x1, h1, l1);
                __nv_bfloat16* rowp = g_valsS + (size_t)(b * SS + q) * E3D + h * HD + n;
                *(uint32_t*)(rowp)          = pack16(h0, h1);
                *(uint32_t*)(rowp + DD)     = pack16(h0, h1);
                *(uint32_t*)(rowp + 2 * DD) = pack16(l0, l1);
            }
        }
    }
}

// ===========================================================================
// Kernel 5: O projection via mma.sync bf16, K=3072 concat split.
// ===========================================================================
__global__ __launch_bounds__(256) void oproj_mma_kernel(
    const float* __restrict__ ob, float* __restrict__ out)
{
    __shared__ __align__(16) __nv_bfloat16 sA[128 * TSTRIDE];
    __shared__ __align__(16) __nv_bfloat16 sB[64 * TSTRIDE];

    const int tid = threadIdx.x;
    const int lane = tid & 31, wid = tid >> 5;
    const int wm = wid & 3, wn = wid >> 2;
    const int m0 = blockIdx.x * 128;
    const int n0 = blockIdx.y * 64;

    const int ar = tid >> 1;
    const int ac = (tid & 1) * 16;
    const __nv_bfloat16* Arow = g_valsS + (size_t)(m0 + ar) * E3D + ac;
    const int vr = tid >> 2;
    const int vc = (tid & 3) * 8;
    const __nv_bfloat16* Brow = g_OWs + (size_t)(n0 + vr) * E3D + vc;

    const uint32_t aB = smem_u32(sA), bB = smem_u32(sB);
    const int a_row = wm * 32 + ((lane >> 3) & 1) * 8 + (lane & 7);
    const int a_kadd = ((lane >> 4) & 1) * 8;
    const int b_row = wn * 32 + ((lane >> 4) & 1) * 8 + (lane & 7);
    const int b_kadd = ((lane >> 3) & 1) * 8;

    float acc[2][4][4];
    #pragma unroll
    for (int i = 0; i < 2; i++)
        #pragma unroll
        for (int j = 0; j < 4; j++)
            #pragma unroll
            for (int r = 0; r < 4; r++) acc[i][j][r] = 0.f;

    uint4 a0, a1, b0;
    a0 = *(const uint4*)(Arow);
    a1 = *(const uint4*)(Arow + 8);
    b0 = *(const uint4*)(Brow);

    const int NCH = E3D / 32;   // 96
    for (int c = 0; c < NCH; ++c) {
        __syncthreads();
        *(uint4*)(sA + ar * TSTRIDE + ac) = a0;
        *(uint4*)(sA + ar * TSTRIDE + ac + 8) = a1;
        *(uint4*)(sB + vr * TSTRIDE + vc) = b0;
        if (c + 1 < NCH) {
            a0 = *(const uint4*)(Arow + (c + 1) * 32);
            a1 = *(const uint4*)(Arow + (c + 1) * 32 + 8);
            b0 = *(const uint4*)(Brow + (c + 1) * 32);
        }
        __syncthreads();

        #pragma unroll
        for (int ks = 0; ks < 2; ++ks) {
            const int kc = ks * 16;
            uint32_t af[2][4], bf[2][4];
            #pragma unroll
            for (int i = 0; i < 2; ++i)
                ldsm4(af[i], aB + (uint32_t)((a_row + i * 16) * TSTRIDE + kc + a_kadd) * 2);
            #pragma unroll
            for (int p = 0; p < 2; ++p)
                ldsm4(bf[p], bB + (uint32_t)((b_row + p * 16) * TSTRIDE + kc + b_kadd) * 2);
            #pragma unroll
            for (int i = 0; i < 2; ++i)
                #pragma unroll
                for (int jn = 0; jn < 4; ++jn) {
                    const int p = jn >> 1, q = (jn & 1) * 2;
                    mma16816(acc[i][jn], af[i], bf[p][q], bf[p][q + 1]);
                }
        }
    }

    const int g = lane >> 2, t = lane & 3;
    #pragma unroll
    for (int i = 0; i < 2; ++i) {
        #pragma unroll
        for (int jn = 0; jn < 4; ++jn) {
            const int n = n0 + wn * 32 + jn * 8 + 2 * t;
            const float bx = ob[n], by = ob[n + 1];
            #pragma unroll
            for (int half = 0; half < 2; ++half) {
                const int m = m0 + wm * 32 + i * 16 + g + half * 8;
                float2 v;
                v.x = acc[i][jn][half * 2 + 0] + bx;
                v.y = acc[i][jn][half * 2 + 1] + by;
                *(float2*)(out + (size_t)m * DD + n) = v;
            }
        }
    }
}

// ===========================================================================
extern "C" void kernel_launch(void* const* d_in, const int* in_sizes, int n_in,
                              void* d_out, int out_size)
{
    const float *x = nullptr, *thr = nullptr, *qkvw = nullptr,
                *qkvb = nullptr, *ow = nullptr, *ob = nullptr;
    for (int i = 0; i < n_in; ++i) {
        const float* p = (const float*)d_in[i];
        switch (in_sizes[i]) {
            case MROWS * DD:   x = p;    break;
            case HH:           thr = p;  break;
            case E3D * DD:     qkvw = p; break;
            case E3D:          qkvb = p; break;
            case DD * DD:      ow = p;   break;
            case DD:           ob = p;   break;
        }
    }
    float* out = (float*)d_out;

    __half *Xh, *Xm, *Xl, *Wh, *Wm, *Wl;
    cudaGetSymbolAddress((void**)&Xh, g_Xh);
    cudaGetSymbolAddress((void**)&Xm, g_Xm);
    cudaGetSymbolAddress((void**)&Xl, g_Xl);
    cudaGetSymbolAddress((void**)&Wh, g_Wh);
    cudaGetSymbolAddress((void**)&Wm, g_Wm);
    cudaGetSymbolAddress((void**)&Wl, g_Wl);

    cudaFuncSetAttribute(qkv_mma_kernel, cudaFuncAttributeMaxDynamicSharedMemorySize, QKV_SMEM);
    cudaFuncSetAttribute(logits_mma_kernel, cudaFuncAttributeMaxDynamicSharedMemorySize, LG_SMEM);

    split3_kernel<<<(MROWS * DD) / 1024, 256>>>(x, Xh, Xm, Xl);
    split3_kernel<<<(E3D * DD) / 1024, 256>>>(qkvw, Wh, Wm, Wl);
    qkv_mma_kernel<<<dim3(MROWS / 128, E3D / 64), 256, QKV_SMEM>>>(qkvb);
    vsplit_kernel<<<dim3(SS / 128, BH), 256>>>();
    owsplit_kernel<<<(DD * DD) / (256 * 4), 256>>>(ow);
    logits_mma_kernel<<<dim3(SS / 128, SS / 64, BH), 256, LG_SMEM>>>();
    rowstats_kernel<<<BH * SS, 256>>>(thr);
    pv_mma_kernel<<<dim3(SS / 128, BH), 256>>>();
    oproj_mma_kernel<<<dim3(MROWS / 128, DD / 64), 256>>>(ob, out);
}